// round 8
// baseline (speedup 1.0000x reference)
#include <cuda_runtime.h>

// Fused y = conv3x3_same(x, w1); z = conv3x3_same(y, w2), [16,1,2048,2048] fp32.
// Register-streaming, incremental accumulation, packed f32x2 FMAs, 8 cols/lane.
// Warp = 256-col strip x 32-row chunk. Rows loaded as ulonglong2 so aligned
// f32 pairs need no packing. 3-deep row prefetch queue; last 3 steps skip the
// (useless) prefetch. No smem, no barriers. y forced to 0 outside the image.

#define IMG_H 2048
#define IMG_W 2048
#define ROWS 32
#define STRIPS 8          // 2048 / 256
#define WARPS_PER_CTA 4

typedef unsigned long long u64;

__device__ __forceinline__ u64 pk(float lo, float hi) {
    u64 r; asm("mov.b64 %0, {%1, %2};" : "=l"(r) : "f"(lo), "f"(hi)); return r;
}
__device__ __forceinline__ float lo32(u64 v) { return __uint_as_float((unsigned)v); }
__device__ __forceinline__ float hi32(u64 v) { return __uint_as_float((unsigned)(v >> 32)); }
__device__ __forceinline__ u64 fma2(u64 a, u64 b, u64 c) {
    u64 d; asm("fma.rn.f32x2 %0, %1, %2, %3;" : "=l"(d) : "l"(a), "l"(b), "l"(c)); return d;
}
__device__ __forceinline__ u64 mul2(u64 a, u64 b) {
    u64 d; asm("mul.rn.f32x2 %0, %1, %2;" : "=l"(d) : "l"(a), "l"(b)); return d;
}

struct Raw { ulonglong2 A, B; float2 h; };     // A=(x0,x1|x2,x3) B=(x4,x5|x6,x7) pairs
struct XP  { u64 P[9]; float ea, eb, ec; };    // P[k] = (x[k-1], x[k])
struct YA  { u64 a[4]; float ae; };
struct YQ  { u64 Q[9]; };
struct ZA  { u64 a[4]; };

template <bool SAFE>
__device__ __forceinline__ Raw ldrow(const float*& lp, const float*& hp,
                                     int& lr, bool hOK)
{
    Raw o;
    bool rv = SAFE || ((unsigned)lr < IMG_H);
    if (rv) {
        o.A = __ldg((const ulonglong2*)lp);
        o.B = __ldg((const ulonglong2*)(lp + 4));
    } else {
        o.A = make_ulonglong2(0ull, 0ull);
        o.B = make_ulonglong2(0ull, 0ull);
    }
    if (hOK && rv) o.h = __ldg((const float2*)hp);
    else           o.h = make_float2(0.f, 0.f);
    lp += IMG_W; hp += IMG_W;
    if (!SAFE) lr++;
    return o;
}

__device__ __forceinline__ XP cvt(const Raw& p, int lane)
{
    float v0 = lo32(p.A.x), v1 = hi32(p.A.x), v2 = lo32(p.A.y), v3 = hi32(p.A.y);
    float v4 = lo32(p.B.x), v5 = hi32(p.B.x), v6 = lo32(p.B.y), v7 = hi32(p.B.y);
    float up = __shfl_up_sync(0xffffffffu, v7, 1);
    float dn = __shfl_down_sync(0xffffffffu, v0, 1);
    float xm1 = (lane == 0)  ? p.h.y : up;    // x[8g-1]
    float xp8 = (lane == 31) ? p.h.x : dn;    // x[8g+8]
    XP x;
    x.P[0] = pk(xm1, v0);
    x.P[1] = p.A.x;            // (v0,v1) free
    x.P[2] = pk(v1, v2);
    x.P[3] = p.A.y;            // (v2,v3) free
    x.P[4] = pk(v3, v4);
    x.P[5] = p.B.x;            // (v4,v5) free
    x.P[6] = pk(v5, v6);
    x.P[7] = p.B.y;            // (v6,v7) free
    x.P[8] = pk(v7, xp8);
    x.ea = (lane == 0) ? p.h.x : v7;
    x.eb = (lane == 0) ? xm1   : xp8;
    x.ec = (lane == 0) ? v0    : p.h.y;
    return x;
}

template <int A, bool FIRST>
__device__ __forceinline__ void addY(YA& y, const XP& x, const u64* W)
{
#pragma unroll
    for (int j = 0; j < 4; j++) {
        u64 t = FIRST ? mul2(W[3*A], x.P[2*j])
                      : fma2(W[3*A], x.P[2*j], y.a[j]);
        t = fma2(W[3*A+1], x.P[2*j+1], t);
        y.a[j] = fma2(W[3*A+2], x.P[2*j+2], t);
    }
    float e = FIRST ? (lo32(W[3*A]) * x.ea)
                    : fmaf(lo32(W[3*A]), x.ea, y.ae);
    e = fmaf(lo32(W[3*A+1]), x.eb, e);
    y.ae = fmaf(lo32(W[3*A+2]), x.ec, e);
}

template <bool SAFE>
__device__ __forceinline__ YQ fin(YA y, bool valid, bool killE, int lane)
{
    if (!SAFE && !valid) {
#pragma unroll
        for (int j = 0; j < 4; j++) y.a[j] = 0ull;
        y.ae = 0.f;
    }
    if (killE) y.ae = 0.f;
    float y0 = lo32(y.a[0]), y7 = hi32(y.a[3]);
    float up = __shfl_up_sync(0xffffffffu, y7, 1);
    float dn = __shfl_down_sync(0xffffffffu, y0, 1);
    float ym1 = (lane == 0)  ? y.ae : up;
    float yp8 = (lane == 31) ? y.ae : dn;
    YQ q;
    q.Q[0] = pk(ym1, y0);
#pragma unroll
    for (int j = 0; j < 4; j++) q.Q[2*j+1] = y.a[j];
#pragma unroll
    for (int j = 1; j < 4; j++) q.Q[2*j] = pk(hi32(y.a[j-1]), lo32(y.a[j]));
    q.Q[8] = pk(y7, yp8);
    return q;
}

template <int A, bool FIRST>
__device__ __forceinline__ void addZ(ZA& z, const YQ& q, const u64* W)
{
#pragma unroll
    for (int j = 0; j < 4; j++) {
        u64 t = FIRST ? mul2(W[3*A], q.Q[2*j])
                      : fma2(W[3*A], q.Q[2*j], z.a[j]);
        t = fma2(W[3*A+1], q.Q[2*j+1], t);
        z.a[j] = fma2(W[3*A+2], q.Q[2*j+2], t);
    }
}

__device__ __forceinline__ void stz(float* p, const ZA& z)
{
    __stcs((float4*)p,       make_float4(lo32(z.a[0]), hi32(z.a[0]),
                                         lo32(z.a[1]), hi32(z.a[1])));
    __stcs((float4*)(p + 4), make_float4(lo32(z.a[2]), hi32(z.a[2]),
                                         lo32(z.a[3]), hi32(z.a[3])));
}

template <bool SAFE>
__device__ __forceinline__ void run(const float* __restrict__ xb,
                                    float* __restrict__ ob,
                                    const float* __restrict__ w1g,
                                    const float* __restrict__ w2g,
                                    int c0, int R0, int lane, bool lE, bool rE)
{
    u64 W1[9], W2[9];
#pragma unroll
    for (int i = 0; i < 9; i++) {
        float a = __ldg(w1g + i); W1[i] = pk(a, a);
        float b = __ldg(w2g + i); W2[i] = pk(b, b);
    }
    const bool hOK   = (lane == 0 && !lE) || (lane == 31 && !rE);
    const bool killE = (lane == 0 && lE) || (lane == 31 && rE);

    const float* lp = xb + (size_t)(R0 - 2) * IMG_W + c0 + 8 * lane;
    const float* hp = lp + ((lane == 31) ? 8 : -2);
    float*     orow = ob + (size_t)R0 * IMG_W + c0 + 8 * lane;
    int lr = R0 - 2;
    int r  = R0;

    // ---- Prologue: rows R0-2 .. R0+4; y(R0-1), y(R0) completed ----
    Raw q0 = ldrow<SAFE>(lp, hp, lr, hOK);
    Raw q1 = ldrow<SAFE>(lp, hp, lr, hOK);
    Raw q2 = ldrow<SAFE>(lp, hp, lr, hOK);

    YA t1, t2, ya, yb, yc;
    ZA za, zb, zc;

    XP A = cvt(q0, lane); q0 = ldrow<SAFE>(lp, hp, lr, hOK);
    addY<0, true >(t1, A, W1);
    XP B = cvt(q1, lane); q1 = ldrow<SAFE>(lp, hp, lr, hOK);
    addY<1, false>(t1, B, W1);
    addY<0, true >(t2, B, W1);
    XP C = cvt(q2, lane); q2 = ldrow<SAFE>(lp, hp, lr, hOK);
    addY<2, false>(t1, C, W1);
    addY<1, false>(t2, C, W1);
    addY<0, true >(ya, C, W1);
    YQ Q = fin<SAFE>(t1, (unsigned)(R0 - 1) < IMG_H, killE, lane);
    addZ<0, true >(za, Q, W2);
    XP D = cvt(q0, lane); q0 = ldrow<SAFE>(lp, hp, lr, hOK);
    addY<2, false>(t2, D, W1);
    addY<1, false>(ya, D, W1);
    addY<0, true >(yb, D, W1);
    Q = fin<SAFE>(t2, true, killE, lane);
    addZ<1, false>(za, Q, W2);
    addZ<0, true >(zb, Q, W2);

#define BODY(P, Y0, Y1, Y2, Z0, Z1, Z2)                                       \
        XP X = cvt(P, lane);                                                  \
        addY<2, false>(Y0, X, W1);                                            \
        addY<1, false>(Y1, X, W1);                                            \
        addY<0, true >(Y2, X, W1);                                            \
        YQ Qs = fin<SAFE>(Y0, (unsigned)(r + 1) < IMG_H, killE, lane);        \
        addZ<2, false>(Z0, Qs, W2);                                           \
        addZ<1, false>(Z1, Qs, W2);                                           \
        addZ<0, true >(Z2, Qs, W2);                                           \
        stz(orow, Z0);                                                        \
        orow += IMG_W; r++

#define STEP(P, Y0, Y1, Y2, Z0, Z1, Z2)                                       \
    do {                                                                      \
        BODY(P, Y0, Y1, Y2, Z0, Z1, Z2);                                      \
        P = ldrow<SAFE>(lp, hp, lr, hOK);                                     \
    } while (0)

#define STEPNL(P, Y0, Y1, Y2, Z0, Z1, Z2)                                     \
    do { BODY(P, Y0, Y1, Y2, Z0, Z1, Z2); } while (0)

    // 29 loading steps (9 triples + 2), then 3 no-load steps. Total 32.
#pragma unroll 1
    for (int i = 0; i < 9; i++) {
        STEP(q1, ya, yb, yc, za, zb, zc);
        STEP(q2, yb, yc, ya, zb, zc, za);
        STEP(q0, yc, ya, yb, zc, za, zb);
    }
    STEP  (q1, ya, yb, yc, za, zb, zc);
    STEP  (q2, yb, yc, ya, zb, zc, za);
    STEPNL(q0, yc, ya, yb, zc, za, zb);
    STEPNL(q1, ya, yb, yc, za, zb, zc);
    STEPNL(q2, yb, yc, ya, zb, zc, za);
#undef STEP
#undef STEPNL
#undef BODY
}

__global__ __launch_bounds__(WARPS_PER_CTA * 32, 3)
void conv2x_w8b(const float* __restrict__ x, const float* __restrict__ w1g,
                const float* __restrict__ w2g, float* __restrict__ out)
{
    const int lane  = threadIdx.x & 31;
    const int wrp   = threadIdx.x >> 5;
    const int strip = blockIdx.x;                       // 0..7
    const int chunk = blockIdx.y * WARPS_PER_CTA + wrp; // 0..63
    const int c0 = strip * 256;
    const int R0 = chunk * ROWS;
    const bool lE = (strip == 0);
    const bool rE = (strip == STRIPS - 1);

    const float* xb = x   + (size_t)blockIdx.z * ((size_t)IMG_H * IMG_W);
    float*       ob = out + (size_t)blockIdx.z * ((size_t)IMG_H * IMG_W);

    if (chunk != 0 && chunk != (IMG_H / ROWS) - 1)
        run<true >(xb, ob, w1g, w2g, c0, R0, lane, lE, rE);
    else
        run<false>(xb, ob, w1g, w2g, c0, R0, lane, lE, rE);
}

extern "C" void kernel_launch(void* const* d_in, const int* in_sizes, int n_in,
                              void* d_out, int out_size)
{
    const float* x  = (const float*)d_in[0];
    const float* w1 = (const float*)d_in[1];
    const float* w2 = (const float*)d_in[2];
    float* out = (float*)d_out;

    const int B = in_sizes[0] / (IMG_H * IMG_W);            // 16
    dim3 grid(STRIPS, (IMG_H / ROWS) / WARPS_PER_CTA, B);   // 8 x 16 x 16 = 2048
    conv2x_w8b<<<grid, WARPS_PER_CTA * 32>>>(x, w1, w2, out);
}